// round 14
// baseline (speedup 1.0000x reference)
#include <cuda_runtime.h>
#include <cuda_fp16.h>

// PairwisePotential1 — warp-per-row coalesced, 8 output rows x 4 cols per
// thread, 3-buffer rotation (10 row loads per 8 output rows).
// The 1/9 normalization is folded into the exp2 arguments:
//   first/9 = 1/9 + sum exp2(-(s*diff)^2 + K*d - log2(9))
// so the epilogue is a single fma per output element.
// s = sqrt(0.5*log2e), K = -0.5*log2(e). Zero padding.
// out = w1 * (first/9) + w2 * (4+4*sqrt2)/9.

#define S 128
#define SS (S * S)
#define FULLM 0xFFFFFFFFu

__device__ __forceinline__ __half2 H2(unsigned u) {
    return *reinterpret_cast<__half2*>(&u);
}
__device__ __forceinline__ unsigned U2(__half2 h) {
    return *reinterpret_cast<unsigned*>(&h);
}

struct Row { unsigned h01, h12, h23, h34, h45; };  // (v0,v1)..(v4,v5), v_k = col 4l-1+k

__device__ __forceinline__ __half2 eterm(__half2 cs, unsigned n,
                                         __half2 LL, __half2 Sn) {
    __half2 ds = __hfma2(H2(n), Sn, cs);             // s*(c - n)
    return h2exp2(__hfma2(__hneg2(ds), ds, LL));     // exp2(L - ds^2)
}

__device__ __forceinline__ void loadrow(Row& RW, const float* rp, bool ok, int lane) {
    float4 m = make_float4(0.f, 0.f, 0.f, 0.f);
    if (ok) m = *(const float4*)rp;
    unsigned p12 = U2(__floats2half2_rn(m.x, m.y));
    unsigned p34 = U2(__floats2half2_rn(m.z, m.w));
    unsigned nb = __shfl_up_sync(FULLM, p34, 1);
    unsigned nd = __shfl_down_sync(FULLM, p12, 1);
    if (lane == 0)  nb = 0u;
    if (lane == 31) nd = 0u;
    RW.h12 = p12; RW.h34 = p34;
    RW.h01 = __byte_perm(nb,  p12, 0x5432);
    RW.h23 = __byte_perm(p12, p34, 0x5432);
    RW.h45 = __byte_perm(p34, nd,  0x5432);
}

__device__ __forceinline__ void outrow(const Row& R0, const Row& R1, const Row& R2,
                                       const float* w1p, const float* w2p, float* op,
                                       __half2 Sp, __half2 Sn,
                                       __half2 L1h, __half2 L2h, __half2 NINTHh) {
    // pair0 = px cols 4l,4l+1 ; pair1 = px cols 4l+2,4l+3
    __half2 cs0 = __hmul2(Sp, H2(R0.h01));
    __half2 a0 = __hadd2(NINTHh, eterm(cs0, R0.h12, L1h, Sn));
    a0 = __hadd2(a0, eterm(cs0, R0.h23, L1h, Sn));
    a0 = __hadd2(a0, eterm(cs0, R1.h01, L1h, Sn));
    a0 = __hadd2(a0, eterm(cs0, R2.h01, L1h, Sn));
    __half2 b0 =     eterm(cs0, R1.h12, L2h, Sn);
    b0 = __hadd2(b0, eterm(cs0, R1.h23, L2h, Sn));
    b0 = __hadd2(b0, eterm(cs0, R2.h12, L2h, Sn));
    b0 = __hadd2(b0, eterm(cs0, R2.h23, L2h, Sn));

    __half2 cs1 = __hmul2(Sp, H2(R0.h23));
    __half2 a1 = __hadd2(NINTHh, eterm(cs1, R0.h34, L1h, Sn));
    a1 = __hadd2(a1, eterm(cs1, R0.h45, L1h, Sn));
    a1 = __hadd2(a1, eterm(cs1, R1.h23, L1h, Sn));
    a1 = __hadd2(a1, eterm(cs1, R2.h23, L1h, Sn));
    __half2 b1 =     eterm(cs1, R1.h34, L2h, Sn);
    b1 = __hadd2(b1, eterm(cs1, R1.h45, L2h, Sn));
    b1 = __hadd2(b1, eterm(cs1, R2.h34, L2h, Sn));
    b1 = __hadd2(b1, eterm(cs1, R2.h45, L2h, Sn));

    float2 f0 = __half22float2(__hadd2(a0, b0));   // = first/9 for px pair0
    float2 f1 = __half22float2(__hadd2(a1, b1));   // = first/9 for px pair1

    const float SECOND = (4.0f + 4.0f * 1.41421356237309504880f) / 9.0f;
    float4 w1v = *(const float4*)w1p;
    float4 w2v = *(const float4*)w2p;
    float4 o;
    o.x = fmaf(w1v.x, f0.x, w2v.x * SECOND);
    o.y = fmaf(w1v.y, f0.y, w2v.y * SECOND);
    o.z = fmaf(w1v.z, f1.x, w2v.z * SECOND);
    o.w = fmaf(w1v.w, f1.y, w2v.w * SECOND);
    *(float4*)op = o;
}

__global__ __launch_bounds__(128) void pp_kernel(
    const float* __restrict__ x,
    const float* __restrict__ w1,
    const float* __restrict__ w2,
    float* __restrict__ out)
{
    int t    = blockIdx.x * blockDim.x + threadIdx.x;
    int lane = t & 31;
    int w    = t >> 5;              // warp id
    int g    = w & 15;              // rowgroup: output rows 8g..8g+7
    int bc   = w >> 4;              // b*C + c
    int c    = bc & 63;
    int x0   = lane << 2;
    int y0   = g << 3;

    const float Kf = -0.5f * 1.44269504088896340736f;     // -0.5*log2(e)
    const float LOG2_9 = 3.16992500144231237f;            // log2(9)
    const float sF = 0.84933300468f;                      // sqrt(0.5*log2e)
    const __half2 Sp  = __float2half2_rn(sF);
    const __half2 Sn  = __float2half2_rn(-sF);
    const __half2 L1h = __float2half2_rn(Kf - LOG2_9);                           // d=1
    const __half2 L2h = __float2half2_rn(Kf * 1.41421356237309504880f - LOG2_9); // d=sqrt2
    const __half2 NINTHh = __float2half2_rn(1.0f / 9.0f);

    const float* xbase = x   + (size_t)bc * SS + y0 * S + x0;
    const float* w1p   = w1  + (size_t)c  * SS + y0 * S + x0;
    const float* w2p   = w2  + (size_t)c  * SS + y0 * S + x0;
    float*       op    = out + (size_t)bc * SS + y0 * S + x0;

    Row R0, R1, R2;
    loadrow(R0, xbase - S,     (g > 0), lane);   // orig row y0-1
    loadrow(R1, xbase,         true,    lane);   // orig row y0
    loadrow(R2, xbase + S,     true,    lane);   // orig row y0+1

#define OROW(A,B,C,K) outrow(A, B, C, w1p + (K)*S, w2p + (K)*S, op + (K)*S, \
                             Sp, Sn, L1h, L2h, NINTHh);

    OROW(R0, R1, R2, 0)
    loadrow(R0, xbase + 2 * S, true, lane);        OROW(R1, R2, R0, 1)
    loadrow(R1, xbase + 3 * S, true, lane);        OROW(R2, R0, R1, 2)
    loadrow(R2, xbase + 4 * S, true, lane);        OROW(R0, R1, R2, 3)
    loadrow(R0, xbase + 5 * S, true, lane);        OROW(R1, R2, R0, 4)
    loadrow(R1, xbase + 6 * S, true, lane);        OROW(R2, R0, R1, 5)
    loadrow(R2, xbase + 7 * S, true, lane);        OROW(R0, R1, R2, 6)
    loadrow(R0, xbase + 8 * S, (g < 15), lane);    OROW(R1, R2, R0, 7)
#undef OROW
}

extern "C" void kernel_launch(void* const* d_in, const int* in_sizes, int n_in,
                              void* d_out, int out_size)
{
    const float* x  = (const float*)d_in[0];
    const float* w1 = (const float*)d_in[1];
    const float* w2 = (const float*)d_in[2];
    float* out = (float*)d_out;

    // 32 px per thread (8 rows x 4 cols); block = 128 threads
    int total = out_size >> 5;
    int threads = 128;
    int blocks = (total + threads - 1) / threads;
    pp_kernel<<<blocks, threads>>>(x, w1, w2, out);
}

// round 15
// speedup vs baseline: 1.0126x; 1.0126x over previous
#include <cuda_runtime.h>
#include <cuda_fp16.h>

// PairwisePotential1 — R13 config (warp-per-row, 4 output rows x 4 cols per
// thread, 3-buffer rotation, block=256) + 1/9 folded into exp2 constants:
//   first/9 = 1/9 + sum exp2(-(s*diff)^2 + K*d - log2(9))
// s = sqrt(0.5*log2e), K = -0.5*log2(e). Zero padding.
// out = w1 * (first/9) + w2 * (4+4*sqrt2)/9.

#define S 128
#define SS (S * S)
#define FULLM 0xFFFFFFFFu

__device__ __forceinline__ __half2 H2(unsigned u) {
    return *reinterpret_cast<__half2*>(&u);
}
__device__ __forceinline__ unsigned U2(__half2 h) {
    return *reinterpret_cast<unsigned*>(&h);
}

struct Row { unsigned h01, h12, h23, h34, h45; };  // (v0,v1)..(v4,v5), v_k = col 4l-1+k

__device__ __forceinline__ __half2 eterm(__half2 cs, unsigned n,
                                         __half2 LL, __half2 Sn) {
    __half2 ds = __hfma2(H2(n), Sn, cs);             // s*(c - n)
    return h2exp2(__hfma2(__hneg2(ds), ds, LL));     // exp2(L - ds^2)
}

__device__ __forceinline__ void loadrow(Row& RW, const float* rp, bool ok, int lane) {
    float4 m = make_float4(0.f, 0.f, 0.f, 0.f);
    if (ok) m = *(const float4*)rp;
    unsigned p12 = U2(__floats2half2_rn(m.x, m.y));
    unsigned p34 = U2(__floats2half2_rn(m.z, m.w));
    unsigned nb = __shfl_up_sync(FULLM, p34, 1);
    unsigned nd = __shfl_down_sync(FULLM, p12, 1);
    if (lane == 0)  nb = 0u;
    if (lane == 31) nd = 0u;
    RW.h12 = p12; RW.h34 = p34;
    RW.h01 = __byte_perm(nb,  p12, 0x5432);
    RW.h23 = __byte_perm(p12, p34, 0x5432);
    RW.h45 = __byte_perm(p34, nd,  0x5432);
}

__device__ __forceinline__ void outrow(const Row& R0, const Row& R1, const Row& R2,
                                       const float* w1p, const float* w2p, float* op,
                                       __half2 Sp, __half2 Sn,
                                       __half2 L1h, __half2 L2h, __half2 NINTHh) {
    // pair0 = px cols 4l,4l+1 ; pair1 = px cols 4l+2,4l+3
    __half2 cs0 = __hmul2(Sp, H2(R0.h01));
    __half2 a0 = __hadd2(NINTHh, eterm(cs0, R0.h12, L1h, Sn));
    a0 = __hadd2(a0, eterm(cs0, R0.h23, L1h, Sn));
    a0 = __hadd2(a0, eterm(cs0, R1.h01, L1h, Sn));
    a0 = __hadd2(a0, eterm(cs0, R2.h01, L1h, Sn));
    __half2 b0 =     eterm(cs0, R1.h12, L2h, Sn);
    b0 = __hadd2(b0, eterm(cs0, R1.h23, L2h, Sn));
    b0 = __hadd2(b0, eterm(cs0, R2.h12, L2h, Sn));
    b0 = __hadd2(b0, eterm(cs0, R2.h23, L2h, Sn));

    __half2 cs1 = __hmul2(Sp, H2(R0.h23));
    __half2 a1 = __hadd2(NINTHh, eterm(cs1, R0.h34, L1h, Sn));
    a1 = __hadd2(a1, eterm(cs1, R0.h45, L1h, Sn));
    a1 = __hadd2(a1, eterm(cs1, R1.h23, L1h, Sn));
    a1 = __hadd2(a1, eterm(cs1, R2.h23, L1h, Sn));
    __half2 b1 =     eterm(cs1, R1.h34, L2h, Sn);
    b1 = __hadd2(b1, eterm(cs1, R1.h45, L2h, Sn));
    b1 = __hadd2(b1, eterm(cs1, R2.h34, L2h, Sn));
    b1 = __hadd2(b1, eterm(cs1, R2.h45, L2h, Sn));

    float2 f0 = __half22float2(__hadd2(a0, b0));   // = first/9 for pair0
    float2 f1 = __half22float2(__hadd2(a1, b1));   // = first/9 for pair1

    const float SECOND = (4.0f + 4.0f * 1.41421356237309504880f) / 9.0f;
    float4 w1v = *(const float4*)w1p;
    float4 w2v = *(const float4*)w2p;
    float4 o;
    o.x = fmaf(w1v.x, f0.x, w2v.x * SECOND);
    o.y = fmaf(w1v.y, f0.y, w2v.y * SECOND);
    o.z = fmaf(w1v.z, f1.x, w2v.z * SECOND);
    o.w = fmaf(w1v.w, f1.y, w2v.w * SECOND);
    *(float4*)op = o;
}

__global__ __launch_bounds__(256) void pp_kernel(
    const float* __restrict__ x,
    const float* __restrict__ w1,
    const float* __restrict__ w2,
    float* __restrict__ out)
{
    int t    = blockIdx.x * blockDim.x + threadIdx.x;
    int lane = t & 31;
    int w    = t >> 5;              // warp id
    int g    = w & 31;              // rowgroup: output rows 4g..4g+3
    int bc   = w >> 5;              // b*C + c
    int c    = bc & 63;
    int x0   = lane << 2;
    int y0   = g << 2;

    const float Kf = -0.5f * 1.44269504088896340736f;     // -0.5*log2(e)
    const float LOG2_9 = 3.16992500144231237f;            // log2(9)
    const float sF = 0.84933300468f;                      // sqrt(0.5*log2e)
    const __half2 Sp  = __float2half2_rn(sF);
    const __half2 Sn  = __float2half2_rn(-sF);
    const __half2 L1h = __float2half2_rn(Kf - LOG2_9);                           // d=1
    const __half2 L2h = __float2half2_rn(Kf * 1.41421356237309504880f - LOG2_9); // d=sqrt2
    const __half2 NINTHh = __float2half2_rn(1.0f / 9.0f);

    const float* xbase = x   + (size_t)bc * SS + y0 * S + x0;
    const float* w1p   = w1  + (size_t)c  * SS + y0 * S + x0;
    const float* w2p   = w2  + (size_t)c  * SS + y0 * S + x0;
    float*       op    = out + (size_t)bc * SS + y0 * S + x0;

    Row R0, R1, R2;
    loadrow(R0, xbase - S,     (g > 0), lane);   // orig row y0-1
    loadrow(R1, xbase,         true,    lane);   // orig row y0
    loadrow(R2, xbase + S,     true,    lane);   // orig row y0+1

#define OROW(A,B,C,K) outrow(A, B, C, w1p + (K)*S, w2p + (K)*S, op + (K)*S, \
                             Sp, Sn, L1h, L2h, NINTHh);

    OROW(R0, R1, R2, 0)
    loadrow(R0, xbase + 2 * S, true, lane);        OROW(R1, R2, R0, 1)
    loadrow(R1, xbase + 3 * S, true, lane);        OROW(R2, R0, R1, 2)
    loadrow(R2, xbase + 4 * S, (g < 31), lane);    OROW(R0, R1, R2, 3)
#undef OROW
}

extern "C" void kernel_launch(void* const* d_in, const int* in_sizes, int n_in,
                              void* d_out, int out_size)
{
    const float* x  = (const float*)d_in[0];
    const float* w1 = (const float*)d_in[1];
    const float* w2 = (const float*)d_in[2];
    float* out = (float*)d_out;

    // 16 px per thread (4 rows x 4 cols), warp covers 128 cols x 4 rows
    int total = out_size >> 4;
    int threads = 256;
    int blocks = (total + threads - 1) / threads;
    pp_kernel<<<blocks, threads>>>(x, w1, w2, out);
}

// round 16
// speedup vs baseline: 1.0312x; 1.0183x over previous
#include <cuda_runtime.h>
#include <cuda_fp16.h>

// PairwisePotential1 — R15 config (warp-per-row, 4 output rows x 4 cols per
// thread, block=256, 1/9 folded into exp2 constants) + software-pipelined row
// loads: the raw float4 LDG for row K+2 is issued before outrow K's compute,
// so LDG latency overlaps ~130 cycles of fma/MUFU work. Packing (F2FP /
// shuffle / PRMT) happens at use.
//   first/9 = 1/9 + sum exp2(-(s*diff)^2 + K*d - log2(9))
// s = sqrt(0.5*log2e), K = -0.5*log2(e). Zero padding.
// out = w1 * (first/9) + w2 * (4+4*sqrt2)/9.

#define S 128
#define SS (S * S)
#define FULLM 0xFFFFFFFFu

__device__ __forceinline__ __half2 H2(unsigned u) {
    return *reinterpret_cast<__half2*>(&u);
}
__device__ __forceinline__ unsigned U2(__half2 h) {
    return *reinterpret_cast<unsigned*>(&h);
}

struct Row { unsigned h01, h12, h23, h34, h45; };  // (v0,v1)..(v4,v5), v_k = col 4l-1+k

__device__ __forceinline__ __half2 eterm(__half2 cs, unsigned n,
                                         __half2 LL, __half2 Sn) {
    __half2 ds = __hfma2(H2(n), Sn, cs);             // s*(c - n)
    return h2exp2(__hfma2(__hneg2(ds), ds, LL));     // exp2(L - ds^2)
}

// Raw load only — no pack. Issued early so LDG latency overlaps compute.
__device__ __forceinline__ float4 loadraw(const float* rp, bool ok) {
    float4 m = make_float4(0.f, 0.f, 0.f, 0.f);
    if (ok) m = *(const float4*)rp;
    return m;
}

// Pack at use time: convert + halo shuffle + shifted-pair PRMTs.
__device__ __forceinline__ void packrow(Row& RW, float4 m, int lane) {
    unsigned p12 = U2(__floats2half2_rn(m.x, m.y));
    unsigned p34 = U2(__floats2half2_rn(m.z, m.w));
    unsigned nb = __shfl_up_sync(FULLM, p34, 1);
    unsigned nd = __shfl_down_sync(FULLM, p12, 1);
    if (lane == 0)  nb = 0u;
    if (lane == 31) nd = 0u;
    RW.h12 = p12; RW.h34 = p34;
    RW.h01 = __byte_perm(nb,  p12, 0x5432);
    RW.h23 = __byte_perm(p12, p34, 0x5432);
    RW.h45 = __byte_perm(p34, nd,  0x5432);
}

__device__ __forceinline__ void outrow(const Row& R0, const Row& R1, const Row& R2,
                                       const float* w1p, const float* w2p, float* op,
                                       __half2 Sp, __half2 Sn,
                                       __half2 L1h, __half2 L2h, __half2 NINTHh) {
    // pair0 = px cols 4l,4l+1 ; pair1 = px cols 4l+2,4l+3
    __half2 cs0 = __hmul2(Sp, H2(R0.h01));
    __half2 a0 = __hadd2(NINTHh, eterm(cs0, R0.h12, L1h, Sn));
    a0 = __hadd2(a0, eterm(cs0, R0.h23, L1h, Sn));
    a0 = __hadd2(a0, eterm(cs0, R1.h01, L1h, Sn));
    a0 = __hadd2(a0, eterm(cs0, R2.h01, L1h, Sn));
    __half2 b0 =     eterm(cs0, R1.h12, L2h, Sn);
    b0 = __hadd2(b0, eterm(cs0, R1.h23, L2h, Sn));
    b0 = __hadd2(b0, eterm(cs0, R2.h12, L2h, Sn));
    b0 = __hadd2(b0, eterm(cs0, R2.h23, L2h, Sn));

    __half2 cs1 = __hmul2(Sp, H2(R0.h23));
    __half2 a1 = __hadd2(NINTHh, eterm(cs1, R0.h34, L1h, Sn));
    a1 = __hadd2(a1, eterm(cs1, R0.h45, L1h, Sn));
    a1 = __hadd2(a1, eterm(cs1, R1.h23, L1h, Sn));
    a1 = __hadd2(a1, eterm(cs1, R2.h23, L1h, Sn));
    __half2 b1 =     eterm(cs1, R1.h34, L2h, Sn);
    b1 = __hadd2(b1, eterm(cs1, R1.h45, L2h, Sn));
    b1 = __hadd2(b1, eterm(cs1, R2.h34, L2h, Sn));
    b1 = __hadd2(b1, eterm(cs1, R2.h45, L2h, Sn));

    float2 f0 = __half22float2(__hadd2(a0, b0));   // = first/9 for pair0
    float2 f1 = __half22float2(__hadd2(a1, b1));   // = first/9 for pair1

    const float SECOND = (4.0f + 4.0f * 1.41421356237309504880f) / 9.0f;
    float4 w1v = *(const float4*)w1p;
    float4 w2v = *(const float4*)w2p;
    float4 o;
    o.x = fmaf(w1v.x, f0.x, w2v.x * SECOND);
    o.y = fmaf(w1v.y, f0.y, w2v.y * SECOND);
    o.z = fmaf(w1v.z, f1.x, w2v.z * SECOND);
    o.w = fmaf(w1v.w, f1.y, w2v.w * SECOND);
    *(float4*)op = o;
}

__global__ __launch_bounds__(256) void pp_kernel(
    const float* __restrict__ x,
    const float* __restrict__ w1,
    const float* __restrict__ w2,
    float* __restrict__ out)
{
    int t    = blockIdx.x * blockDim.x + threadIdx.x;
    int lane = t & 31;
    int w    = t >> 5;              // warp id
    int g    = w & 31;              // rowgroup: output rows 4g..4g+3
    int bc   = w >> 5;              // b*C + c
    int c    = bc & 63;
    int x0   = lane << 2;
    int y0   = g << 2;

    const float Kf = -0.5f * 1.44269504088896340736f;     // -0.5*log2(e)
    const float LOG2_9 = 3.16992500144231237f;            // log2(9)
    const float sF = 0.84933300468f;                      // sqrt(0.5*log2e)
    const __half2 Sp  = __float2half2_rn(sF);
    const __half2 Sn  = __float2half2_rn(-sF);
    const __half2 L1h = __float2half2_rn(Kf - LOG2_9);                           // d=1
    const __half2 L2h = __float2half2_rn(Kf * 1.41421356237309504880f - LOG2_9); // d=sqrt2
    const __half2 NINTHh = __float2half2_rn(1.0f / 9.0f);

    const float* xbase = x   + (size_t)bc * SS + y0 * S + x0;
    const float* w1p   = w1  + (size_t)c  * SS + y0 * S + x0;
    const float* w2p   = w2  + (size_t)c  * SS + y0 * S + x0;
    float*       op    = out + (size_t)bc * SS + y0 * S + x0;

    // Batch the first three row LDGs (MLP=3), then pack.
    float4 m0 = loadraw(xbase - S, (g > 0));
    float4 m1 = loadraw(xbase,     true);
    float4 m2 = loadraw(xbase + S, true);
    Row R0, R1, R2;
    packrow(R0, m0, lane);
    packrow(R1, m1, lane);
    packrow(R2, m2, lane);

#define OROW(A,B,C,K) outrow(A, B, C, w1p + (K)*S, w2p + (K)*S, op + (K)*S, \
                             Sp, Sn, L1h, L2h, NINTHh);

    // Prefetch row K+2's float4 before computing outrow K.
    float4 mn;
    mn = loadraw(xbase + 2 * S, true);       OROW(R0, R1, R2, 0)
    packrow(R0, mn, lane);
    mn = loadraw(xbase + 3 * S, true);       OROW(R1, R2, R0, 1)
    packrow(R1, mn, lane);
    mn = loadraw(xbase + 4 * S, (g < 31));   OROW(R2, R0, R1, 2)
    packrow(R2, mn, lane);
    OROW(R0, R1, R2, 3)
#undef OROW
}

extern "C" void kernel_launch(void* const* d_in, const int* in_sizes, int n_in,
                              void* d_out, int out_size)
{
    const float* x  = (const float*)d_in[0];
    const float* w1 = (const float*)d_in[1];
    const float* w2 = (const float*)d_in[2];
    float* out = (float*)d_out;

    // 16 px per thread (4 rows x 4 cols), warp covers 128 cols x 4 rows
    int total = out_size >> 4;
    int threads = 256;
    int blocks = (total + threads - 1) / threads;
    pp_kernel<<<blocks, threads>>>(x, w1, w2, out);
}